// round 16
// baseline (speedup 1.0000x reference)
#include <cuda_runtime.h>
#include <cuda_bf16.h>
#include <cstdint>

// DotProductAttention [2048,2,16,64] fp32, unscaled scores.
// HMMA split flash attention, r=2 register blocking (32 rows/warp),
// BM=128 / 128 threads / 2 CTAs/SM.
// QK: bf16 3-product (err ~2e-5). PV: single fp16 GEMM (err ~2e-4).
// Lazy online-max with lane-local grow test (exact skip).
// R16: the per-iteration __syncthreads rendezvous is replaced by a
// producer/consumer barrier web (bar.arrive/bar.sync, parity-alternated)
// so warps can slip up to ~0.5 iteration instead of being hard-coupled:
//   WK[t&1] (ids 1/2): K(t) stores done   -> sync at iter-t start
//   WV[t&1] (ids 3/4): V(t) stores done   -> sync after G1(t)
//   R [t&1] (ids 5/6): tile-t reads done  -> sync before iter-(t+1) K stores
#define SQc     2048
#define RSTRIDE 2048
#define BM      128
#define BN      64
#define NTH     128
#define NKT     (SQc / BN)
#define LOG2E   1.4426950408889634f
#define LDH     72                    // half-element row stride (144 B)

// smem byte offsets
#define S_QH   0                       // 128 x 72 halves = 18432 B
#define S_QL   18432
#define S_KV0  36864                   // two K/V buffers, 27648 B each
#define KVBUF  27648
#define KH_REL 0                       // 64 x 72 halves = 9216 B per plane
#define KL_REL 9216
#define VH_REL 18432                   // fp16 V, single plane
#define SMEM_TOTAL (36864 + 2 * 27648)   // 92160 B -> 2 CTAs/SM

#define BAR_SYNC(id)   asm volatile("bar.sync %0, 256;"   :: "r"(id) : "memory")
#define BAR_ARRIVE(id) asm volatile("bar.arrive %0, 256;" :: "r"(id) : "memory")
#define FENCE_CTA()    asm volatile("membar.cta;" ::: "memory")

__device__ __forceinline__ uint32_t smem_u32(const void* p) {
    uint32_t a;
    asm("{ .reg .u64 t; cvta.to.shared.u64 t, %1; cvt.u32.u64 %0, t; }" : "=r"(a) : "l"(p));
    return a;
}
__device__ __forceinline__ float ex2(float x) {
    float r; asm("ex2.approx.ftz.f32 %0, %1;" : "=f"(r) : "f"(x)); return r;
}
__device__ __forceinline__ uint32_t packbf2(float vhi, float vlo) {
    uint32_t r; asm("cvt.rn.bf16x2.f32 %0, %1, %2;" : "=r"(r) : "f"(vhi), "f"(vlo)); return r;
}
__device__ __forceinline__ uint32_t packf16(float vhi, float vlo) {
    uint32_t r; asm("cvt.rn.f16x2.f32 %0, %1, %2;" : "=r"(r) : "f"(vhi), "f"(vlo)); return r;
}
__device__ __forceinline__ float lo_f(uint32_t w) { return __uint_as_float(w << 16); }
__device__ __forceinline__ float hi_f(uint32_t w) { return __uint_as_float(w & 0xffff0000u); }

#define LDSM4(r0, r1, r2, r3, a) \
    asm volatile("ldmatrix.sync.aligned.m8n8.x4.shared.b16 {%0,%1,%2,%3}, [%4];" \
                 : "=r"(r0), "=r"(r1), "=r"(r2), "=r"(r3) : "r"(a))
#define LDSM4T(r0, r1, r2, r3, a) \
    asm volatile("ldmatrix.sync.aligned.m8n8.x4.trans.shared.b16 {%0,%1,%2,%3}, [%4];" \
                 : "=r"(r0), "=r"(r1), "=r"(r2), "=r"(r3) : "r"(a))
#define MMA16816(c, a, b0, b1) \
    asm volatile("mma.sync.aligned.m16n8k16.row.col.f32.bf16.bf16.f32 " \
                 "{%0,%1,%2,%3}, {%4,%5,%6,%7}, {%8,%9}, {%0,%1,%2,%3};" \
                 : "+f"((c)[0]), "+f"((c)[1]), "+f"((c)[2]), "+f"((c)[3]) \
                 : "r"((a)[0]), "r"((a)[1]), "r"((a)[2]), "r"((a)[3]), "r"(b0), "r"(b1))
#define MMAH16816(c, a, b0, b1) \
    asm volatile("mma.sync.aligned.m16n8k16.row.col.f32.f16.f16.f32 " \
                 "{%0,%1,%2,%3}, {%4,%5,%6,%7}, {%8,%9}, {%0,%1,%2,%3};" \
                 : "+f"((c)[0]), "+f"((c)[1]), "+f"((c)[2]), "+f"((c)[3]) \
                 : "r"((a)[0]), "r"((a)[1]), "r"((a)[2]), "r"((a)[3]), "r"(b0), "r"(b1))

// fp32 x8 -> bf16 hi x8 (16B) + lo residual x8 (16B)
__device__ __forceinline__ void cvt8_store(float4 a, float4 b, char* hp, char* lp) {
    uint32_t h0 = packbf2(a.y, a.x);
    uint32_t h1 = packbf2(a.w, a.z);
    uint32_t h2 = packbf2(b.y, b.x);
    uint32_t h3 = packbf2(b.w, b.z);
    uint32_t l0 = packbf2(a.y - hi_f(h0), a.x - lo_f(h0));
    uint32_t l1 = packbf2(a.w - hi_f(h1), a.z - lo_f(h1));
    uint32_t l2 = packbf2(b.y - hi_f(h2), b.x - lo_f(h2));
    uint32_t l3 = packbf2(b.w - hi_f(h3), b.z - lo_f(h3));
    *(uint4*)hp = make_uint4(h0, h1, h2, h3);
    *(uint4*)lp = make_uint4(l0, l1, l2, l3);
}
// fp32 x8 -> fp16 x8 (16B, single plane)
__device__ __forceinline__ void cvt8_store_f16(float4 a, float4 b, char* hp) {
    uint32_t h0 = packf16(a.y, a.x);
    uint32_t h1 = packf16(a.w, a.z);
    uint32_t h2 = packf16(b.y, b.x);
    uint32_t h3 = packf16(b.w, b.z);
    *(uint4*)hp = make_uint4(h0, h1, h2, h3);
}

__global__ __launch_bounds__(NTH, 2)
void attn_hmma(const float* __restrict__ Q, const float* __restrict__ K,
               const float* __restrict__ V, float* __restrict__ Og) {
    extern __shared__ char smc[];
    const uint32_t sb = smem_u32(smc);
    const int tid = threadIdx.x;
    const int wid = tid >> 5;
    const int lane = tid & 31;
    const int g  = lane >> 2;         // quad row
    const int tg = lane & 3;          // quad col
    const int bh = blockIdx.y;
    const int bhoff = (bh >> 4) * 1024 + (bh & 15) * 64;
    const int qbase = blockIdx.x * BM;

    // ---- fill geometry: 128 threads cover a 64x64 tile in 4 chunks of 8 ----
    const int frow = tid >> 3, fd0 = (tid & 7) * 8;   // rows step +16 per chunk
    const size_t goffF = (size_t)frow * RSTRIDE + bhoff + fd0;
    const int soffF = (frow * LDH + fd0) * 2;

    // ---- Q tile fp32 -> bf16 hi/lo into smem (128 rows) ----
    #pragma unroll
    for (int i = 0; i < 8; i++) {
        int c = tid + NTH * i;                // 1024 chunks of 8 elems
        int row = c >> 3, d0 = (c & 7) * 8;
        const float* gq = Q + (size_t)(qbase + row) * RSTRIDE + bhoff + d0;
        float4 a = *(const float4*)gq;
        float4 b = *(const float4*)(gq + 4);
        int off = (row * LDH + d0) * 2;
        cvt8_store(a, b, smc + S_QH + off, smc + S_QL + off);
    }

    // ---- prologue: fill K/V tile 0 into buffer 0 ----
    {
        char* b0 = smc + S_KV0;
        #pragma unroll
        for (int i = 0; i < 4; i++) {
            const float* gk = K + goffF + (size_t)i * 16 * RSTRIDE;
            float4 a = *(const float4*)gk, b = *(const float4*)(gk + 4);
            cvt8_store(a, b, b0 + KH_REL + soffF + i * (16 * LDH * 2),
                             b0 + KL_REL + soffF + i * (16 * LDH * 2));
            const float* gv = V + goffF + (size_t)i * 16 * RSTRIDE;
            float4 av = *(const float4*)gv, bv = *(const float4*)(gv + 4);
            cvt8_store_f16(av, bv, b0 + VH_REL + soffF + i * (16 * LDH * 2));
        }
    }

    // ---- per-lane ldmatrix offsets ----
    const int lb8  = (lane >> 3) & 1;
    const int lb16 = (lane >> 4) & 1;
    const uint32_t aQb0 = sb + ((wid * 32 +      (lane & 15)) * LDH + 8 * lb16) * 2;
    const uint32_t aQb1 = sb + ((wid * 32 + 16 + (lane & 15)) * LDH + 8 * lb16) * 2;
    const uint32_t bKoff = ((8 * lb16 + (lane & 7)) * LDH + 8 * lb8) * 2;
    const uint32_t bVoff = ((8 * lb8 + (lane & 7)) * LDH + 8 * lb16) * 2;

    float o[2][8][4];
    #pragma unroll
    for (int bb = 0; bb < 2; bb++)
        #pragma unroll
        for (int j = 0; j < 8; j++)
            #pragma unroll
            for (int c = 0; c < 4; c++) o[bb][j][c] = 0.f;
    float ls[2][2] = {{0.f, 0.f}, {0.f, 0.f}};
    float mrow[2][2] = {{-1e30f, -1e30f}, {-1e30f, -1e30f}};
    float nb[2][2]   = {{0.f, 0.f}, {0.f, 0.f}};   // mrow*LOG2E, lazily updated

    __syncthreads();   // Q smem + K/V buffer 0 visible (covers WK/WV for kt=0)

    for (int kt = 0; kt < NKT; kt++) {
        const uint32_t cur = sb + S_KV0 + (uint32_t)(kt & 1) * KVBUF;
        const uint32_t bK = cur + bKoff;
        const uint32_t bV = cur + bVoff;
        char* nx = smc + S_KV0 + ((kt + 1) & 1) * KVBUF;
        const bool haveNext = (kt + 1 < NKT);
        const size_t kb = (size_t)(kt + 1) * BN * RSTRIDE;
        float4 pA[4], pB[4];

        // WK sync: K(kt) stores (issued during iter kt-1) are complete.
        if (kt) BAR_SYNC(1 + (kt & 1));

        float s[2][8][4];
        #pragma unroll
        for (int bb = 0; bb < 2; bb++)
            #pragma unroll
            for (int j = 0; j < 8; j++)
                #pragma unroll
                for (int c = 0; c < 4; c++) s[bb][j][c] = 0.f;

        // ---- GEMM1: both row blocks share every K B-fragment ----
        #pragma unroll
        for (int kk = 0; kk < 4; kk++) {
            uint32_t aQH0[4], aQL0[4], aQH1[4], aQL1[4];
            LDSM4(aQH0[0], aQH0[1], aQH0[2], aQH0[3], aQb0 + S_QH + kk * 32);
            LDSM4(aQL0[0], aQL0[1], aQL0[2], aQL0[3], aQb0 + S_QL + kk * 32);
            LDSM4(aQH1[0], aQH1[1], aQH1[2], aQH1[3], aQb1 + S_QH + kk * 32);
            LDSM4(aQL1[0], aQL1[1], aQL1[2], aQL1[3], aQb1 + S_QL + kk * 32);
            #pragma unroll
            for (int j2 = 0; j2 < 4; j2++) {
                uint32_t b0, b1, b2, b3;
                LDSM4(b0, b1, b2, b3, bK + KH_REL + j2 * (16 * LDH * 2) + kk * 32);
                MMA16816(s[0][2 * j2],     aQH0, b0, b1);
                MMA16816(s[0][2 * j2 + 1], aQH0, b2, b3);
                MMA16816(s[1][2 * j2],     aQH1, b0, b1);
                MMA16816(s[1][2 * j2 + 1], aQH1, b2, b3);
                MMA16816(s[0][2 * j2],     aQL0, b0, b1);
                MMA16816(s[0][2 * j2 + 1], aQL0, b2, b3);
                MMA16816(s[1][2 * j2],     aQL1, b0, b1);
                MMA16816(s[1][2 * j2 + 1], aQL1, b2, b3);
                uint32_t c0, c1, c2, c3;
                LDSM4(c0, c1, c2, c3, bK + KL_REL + j2 * (16 * LDH * 2) + kk * 32);
                MMA16816(s[0][2 * j2],     aQH0, c0, c1);
                MMA16816(s[0][2 * j2 + 1], aQH0, c2, c3);
                MMA16816(s[1][2 * j2],     aQH1, c0, c1);
                MMA16816(s[1][2 * j2 + 1], aQH1, c2, c3);
            }
            if (kk == 0 && haveNext) {
                // issue next K global loads early
                #pragma unroll
                for (int i = 0; i < 4; i++) {
                    const float* gp = K + kb + goffF + (size_t)i * 16 * RSTRIDE;
                    pA[i] = *(const float4*)gp;
                    pB[i] = *(const float4*)(gp + 4);
                }
            }
        }

        // WV sync: V(kt) stores (issued during iter kt-1) are complete.
        if (kt) BAR_SYNC(3 + (kt & 1));

        // ---- prefetch G2 chunk-0 V fragments (independent of softmax) ----
        uint32_t vb[4][2], vc[4][2];
        #pragma unroll
        for (int j2 = 0; j2 < 4; j2++) {
            LDSM4T(vb[j2][0], vb[j2][1], vc[j2][0], vc[j2][1],
                   bV + VH_REL + 0 * (16 * LDH * 2) + j2 * 32);
        }

        // ---- lane-local maxima; full reduce + rescale only when grown ----
        float mx[2][2];
        #pragma unroll
        for (int bb = 0; bb < 2; bb++) {
            float mx0 = -1e30f, mx1 = -1e30f;
            #pragma unroll
            for (int j = 0; j < 8; j++) {
                mx0 = fmaxf(mx0, fmaxf(s[bb][j][0], s[bb][j][1]));
                mx1 = fmaxf(mx1, fmaxf(s[bb][j][2], s[bb][j][3]));
            }
            mx[bb][0] = mx0; mx[bb][1] = mx1;
        }
        const bool grew = (mx[0][0] > mrow[0][0]) | (mx[0][1] > mrow[0][1]) |
                          (mx[1][0] > mrow[1][0]) | (mx[1][1] > mrow[1][1]);
        if (__any_sync(0xffffffffu, grew)) {
            #pragma unroll
            for (int bb = 0; bb < 2; bb++) {
                float mx0 = mx[bb][0], mx1 = mx[bb][1];
                mx0 = fmaxf(mx0, __shfl_xor_sync(0xffffffffu, mx0, 1));
                mx0 = fmaxf(mx0, __shfl_xor_sync(0xffffffffu, mx0, 2));
                mx1 = fmaxf(mx1, __shfl_xor_sync(0xffffffffu, mx1, 1));
                mx1 = fmaxf(mx1, __shfl_xor_sync(0xffffffffu, mx1, 2));
                float mn0 = fmaxf(mrow[bb][0], mx0);
                float mn1 = fmaxf(mrow[bb][1], mx1);
                float corr0 = ex2((mrow[bb][0] - mn0) * LOG2E);
                float corr1 = ex2((mrow[bb][1] - mn1) * LOG2E);
                mrow[bb][0] = mn0; mrow[bb][1] = mn1;
                nb[bb][0] = mn0 * LOG2E; nb[bb][1] = mn1 * LOG2E;
                ls[bb][0] *= corr0; ls[bb][1] *= corr1;
                #pragma unroll
                for (int j = 0; j < 8; j++) {
                    o[bb][j][0] *= corr0; o[bb][j][1] *= corr0;
                    o[bb][j][2] *= corr1; o[bb][j][3] *= corr1;
                }
            }
        }

        // ---- phase 2, software-pipelined: sm(kk+1) issues before G2(kk) ----
        uint32_t PH[2][2][4];   // [parity][block][frag]  (fp16 P)

        // sm chunk 0 -> parity 0
        #pragma unroll
        for (int bb = 0; bb < 2; bb++) {
            float* s0 = s[bb][0];
            float* s1 = s[bb][1];
            s0[0] = ex2(fmaf(s0[0], LOG2E, -nb[bb][0]));
            s0[1] = ex2(fmaf(s0[1], LOG2E, -nb[bb][0]));
            s0[2] = ex2(fmaf(s0[2], LOG2E, -nb[bb][1]));
            s0[3] = ex2(fmaf(s0[3], LOG2E, -nb[bb][1]));
            s1[0] = ex2(fmaf(s1[0], LOG2E, -nb[bb][0]));
            s1[1] = ex2(fmaf(s1[1], LOG2E, -nb[bb][0]));
            s1[2] = ex2(fmaf(s1[2], LOG2E, -nb[bb][1]));
            s1[3] = ex2(fmaf(s1[3], LOG2E, -nb[bb][1]));
            ls[bb][0] += s0[0] + s0[1] + s1[0] + s1[1];
            ls[bb][1] += s0[2] + s0[3] + s1[2] + s1[3];
            PH[0][bb][0] = packf16(s0[1], s0[0]);
            PH[0][bb][1] = packf16(s0[3], s0[2]);
            PH[0][bb][2] = packf16(s1[1], s1[0]);
            PH[0][bb][3] = packf16(s1[3], s1[2]);
        }

        #pragma unroll
        for (int kk = 0; kk < 4; kk++) {
            const int pc = kk & 1, pn = (kk + 1) & 1;

            // sm chunk kk+1 -> parity pn (hides under G2(kk) MMA drain below)
            if (kk < 3) {
                const int j = 2 * (kk + 1), j1 = 2 * (kk + 1) + 1;
                #pragma unroll
                for (int bb = 0; bb < 2; bb++) {
                    float* s0 = s[bb][j];
                    float* s1 = s[bb][j1];
                    s0[0] = ex2(fmaf(s0[0], LOG2E, -nb[bb][0]));
                    s0[1] = ex2(fmaf(s0[1], LOG2E, -nb[bb][0]));
                    s0[2] = ex2(fmaf(s0[2], LOG2E, -nb[bb][1]));
                    s0[3] = ex2(fmaf(s0[3], LOG2E, -nb[bb][1]));
                    s1[0] = ex2(fmaf(s1[0], LOG2E, -nb[bb][0]));
                    s1[1] = ex2(fmaf(s1[1], LOG2E, -nb[bb][0]));
                    s1[2] = ex2(fmaf(s1[2], LOG2E, -nb[bb][1]));
                    s1[3] = ex2(fmaf(s1[3], LOG2E, -nb[bb][1]));
                    ls[bb][0] += s0[0] + s0[1] + s1[0] + s1[1];
                    ls[bb][1] += s0[2] + s0[3] + s1[2] + s1[3];
                    PH[pn][bb][0] = packf16(s0[1], s0[0]);
                    PH[pn][bb][1] = packf16(s0[3], s0[2]);
                    PH[pn][bb][2] = packf16(s1[1], s1[0]);
                    PH[pn][bb][3] = packf16(s1[3], s1[2]);
                }
            }

            if (kk == 1 && haveNext) {
                // R sync: all warps finished reading tile kt-1 (the buffer
                // these stores overwrite). Arrives were issued post-G2b(kt-1).
                if (kt) BAR_SYNC(5 + ((kt - 1) & 1));
                // store next K
                #pragma unroll
                for (int i = 0; i < 4; i++)
                    cvt8_store(pA[i], pB[i],
                               nx + KH_REL + soffF + i * (16 * LDH * 2),
                               nx + KL_REL + soffF + i * (16 * LDH * 2));
                // WK arrive: K(kt+1) stores done (fence: bar.arrive has no
                // implicit membar).
                FENCE_CTA();
                BAR_ARRIVE(1 + ((kt + 1) & 1));
                // issue next V loads
                #pragma unroll
                for (int i = 0; i < 4; i++) {
                    const float* gp = V + kb + goffF + (size_t)i * 16 * RSTRIDE;
                    pA[i] = *(const float4*)gp;
                    pB[i] = *(const float4*)(gp + 4);
                }
            }
            if (kk == 3 && haveNext) {
                // store next V (current G2 reads cur buffer, no conflict)
                #pragma unroll
                for (int i = 0; i < 4; i++)
                    cvt8_store_f16(pA[i], pB[i],
                                   nx + VH_REL + soffF + i * (16 * LDH * 2));
                // WV arrive: V(kt+1) stores done.
                FENCE_CTA();
                BAR_ARRIVE(3 + ((kt + 1) & 1));
            }

            // G2 chunk kk: O += P_f16 . V_f16  [parity pc]
            if (kk == 0) {
                #pragma unroll
                for (int j2 = 0; j2 < 4; j2++) {
                    MMAH16816(o[0][2 * j2],     PH[0][0], vb[j2][0], vb[j2][1]);
                    MMAH16816(o[0][2 * j2 + 1], PH[0][0], vc[j2][0], vc[j2][1]);
                    MMAH16816(o[1][2 * j2],     PH[0][1], vb[j2][0], vb[j2][1]);
                    MMAH16816(o[1][2 * j2 + 1], PH[0][1], vc[j2][0], vc[j2][1]);
                }
            } else {
                #pragma unroll
                for (int j2 = 0; j2 < 4; j2++) {
                    uint32_t b0, b1, b2, b3;
                    LDSM4T(b0, b1, b2, b3, bV + VH_REL + kk * (16 * LDH * 2) + j2 * 32);
                    MMAH16816(o[0][2 * j2],     PH[pc][0], b0, b1);
                    MMAH16816(o[0][2 * j2 + 1], PH[pc][0], b2, b3);
                    MMAH16816(o[1][2 * j2],     PH[pc][1], b0, b1);
                    MMAH16816(o[1][2 * j2 + 1], PH[pc][1], b2, b3);
                }
            }
        }

        // R arrive: this warp's reads of tile kt (G1 K + G2 V) are complete
        // (values consumed by MMAs). Consumer: sync R in iter kt+1 -- which
        // executes only when iter kt+1 itself stores (kt+1 <= NKT-2).
        if (kt + 3 <= NKT) BAR_ARRIVE(5 + (kt & 1));
    }

    // ---- epilogue: quad-reduce deferred sums, normalize, store ----
    #pragma unroll
    for (int bb = 0; bb < 2; bb++) {
        float l0 = ls[bb][0], l1 = ls[bb][1];
        l0 += __shfl_xor_sync(0xffffffffu, l0, 1);
        l0 += __shfl_xor_sync(0xffffffffu, l0, 2);
        l1 += __shfl_xor_sync(0xffffffffu, l1, 1);
        l1 += __shfl_xor_sync(0xffffffffu, l1, 2);
        float inv0 = 1.f / l0, inv1 = 1.f / l1;
        const int orow = qbase + wid * 32 + bb * 16 + g;
        float* d0p = Og + (size_t)orow * RSTRIDE + bhoff + 2 * tg;
        float* d1p = d0p + 8 * RSTRIDE;
        #pragma unroll
        for (int j = 0; j < 8; j++) {
            *(float2*)(d0p + 8 * j) = make_float2(o[bb][j][0] * inv0, o[bb][j][1] * inv0);
            *(float2*)(d1p + 8 * j) = make_float2(o[bb][j][2] * inv1, o[bb][j][3] * inv1);
        }
    }
}

extern "C" void kernel_launch(void* const* d_in, const int* in_sizes, int n_in,
                              void* d_out, int out_size) {
    const float* Q = (const float*)d_in[0];
    const float* K = (const float*)d_in[1];
    const float* V = (const float*)d_in[2];
    float* O = (float*)d_out;

    cudaFuncSetAttribute(attn_hmma, cudaFuncAttributeMaxDynamicSharedMemorySize, SMEM_TOTAL);
    dim3 grid(SQc / BM, 32);
    attn_hmma<<<grid, NTH, SMEM_TOTAL>>>(Q, K, V, O);
}

// round 17
// speedup vs baseline: 1.0490x; 1.0490x over previous
#include <cuda_runtime.h>
#include <cuda_bf16.h>
#include <cstdint>

// DotProductAttention [2048,2,16,64] fp32, unscaled scores.
// HMMA split flash attention, r=2 register blocking (32 rows/warp),
// BM=128 / 128 threads / 2 CTAs/SM.
// QK: bf16 3-product (err ~2e-5). PV: single fp16 GEMM.
// R17: softmax exponentials via ex2.approx.f16x2 (2 p's per MUFU op,
// produced directly in fragment layout) and row sums via a ones-column
// GEMM (P . 1) accumulated in fp32 -- removes all FADD sums and the
// epilogue shuffle reductions. Lazy online-max with lane-local grow test.
#define SQc     2048
#define RSTRIDE 2048
#define BM      128
#define BN      64
#define NTH     128
#define NKT     (SQc / BN)
#define LOG2E   1.4426950408889634f
#define LDH     72                    // half-element row stride (144 B)
#define ONESF16 0x3C003C00u           // fp16 {1.0, 1.0}

// smem byte offsets
#define S_QH   0                       // 128 x 72 halves = 18432 B
#define S_QL   18432
#define S_KV0  36864                   // two K/V buffers, 27648 B each
#define KVBUF  27648
#define KH_REL 0                       // 64 x 72 halves = 9216 B per plane
#define KL_REL 9216
#define VH_REL 18432                   // fp16 V, single plane
#define SMEM_TOTAL (36864 + 2 * 27648)   // 92160 B -> 2 CTAs/SM

__device__ __forceinline__ uint32_t smem_u32(const void* p) {
    uint32_t a;
    asm("{ .reg .u64 t; cvta.to.shared.u64 t, %1; cvt.u32.u64 %0, t; }" : "=r"(a) : "l"(p));
    return a;
}
__device__ __forceinline__ float ex2(float x) {
    float r; asm("ex2.approx.ftz.f32 %0, %1;" : "=f"(r) : "f"(x)); return r;
}
// two fp16 exp2 in one MUFU op; input/output are f16x2 words
__device__ __forceinline__ uint32_t h2ex2(uint32_t w) {
    uint32_t r; asm("ex2.approx.f16x2 %0, %1;" : "=r"(r) : "r"(w)); return r;
}
__device__ __forceinline__ uint32_t packbf2(float vhi, float vlo) {
    uint32_t r; asm("cvt.rn.bf16x2.f32 %0, %1, %2;" : "=r"(r) : "f"(vhi), "f"(vlo)); return r;
}
__device__ __forceinline__ uint32_t packf16(float vhi, float vlo) {
    uint32_t r; asm("cvt.rn.f16x2.f32 %0, %1, %2;" : "=r"(r) : "f"(vhi), "f"(vlo)); return r;
}
__device__ __forceinline__ float lo_f(uint32_t w) { return __uint_as_float(w << 16); }
__device__ __forceinline__ float hi_f(uint32_t w) { return __uint_as_float(w & 0xffff0000u); }

#define LDSM4(r0, r1, r2, r3, a) \
    asm volatile("ldmatrix.sync.aligned.m8n8.x4.shared.b16 {%0,%1,%2,%3}, [%4];" \
                 : "=r"(r0), "=r"(r1), "=r"(r2), "=r"(r3) : "r"(a))
#define LDSM4T(r0, r1, r2, r3, a) \
    asm volatile("ldmatrix.sync.aligned.m8n8.x4.trans.shared.b16 {%0,%1,%2,%3}, [%4];" \
                 : "=r"(r0), "=r"(r1), "=r"(r2), "=r"(r3) : "r"(a))
#define MMA16816(c, a, b0, b1) \
    asm volatile("mma.sync.aligned.m16n8k16.row.col.f32.bf16.bf16.f32 " \
                 "{%0,%1,%2,%3}, {%4,%5,%6,%7}, {%8,%9}, {%0,%1,%2,%3};" \
                 : "+f"((c)[0]), "+f"((c)[1]), "+f"((c)[2]), "+f"((c)[3]) \
                 : "r"((a)[0]), "r"((a)[1]), "r"((a)[2]), "r"((a)[3]), "r"(b0), "r"(b1))
#define MMAH16816(c, a, b0, b1) \
    asm volatile("mma.sync.aligned.m16n8k16.row.col.f32.f16.f16.f32 " \
                 "{%0,%1,%2,%3}, {%4,%5,%6,%7}, {%8,%9}, {%0,%1,%2,%3};" \
                 : "+f"((c)[0]), "+f"((c)[1]), "+f"((c)[2]), "+f"((c)[3]) \
                 : "r"((a)[0]), "r"((a)[1]), "r"((a)[2]), "r"((a)[3]), "r"(b0), "r"(b1))

// fp32 x8 -> bf16 hi x8 (16B) + lo residual x8 (16B)
__device__ __forceinline__ void cvt8_store(float4 a, float4 b, char* hp, char* lp) {
    uint32_t h0 = packbf2(a.y, a.x);
    uint32_t h1 = packbf2(a.w, a.z);
    uint32_t h2 = packbf2(b.y, b.x);
    uint32_t h3 = packbf2(b.w, b.z);
    uint32_t l0 = packbf2(a.y - hi_f(h0), a.x - lo_f(h0));
    uint32_t l1 = packbf2(a.w - hi_f(h1), a.z - lo_f(h1));
    uint32_t l2 = packbf2(b.y - hi_f(h2), b.x - lo_f(h2));
    uint32_t l3 = packbf2(b.w - hi_f(h3), b.z - lo_f(h3));
    *(uint4*)hp = make_uint4(h0, h1, h2, h3);
    *(uint4*)lp = make_uint4(l0, l1, l2, l3);
}
// fp32 x8 -> fp16 x8 (16B, single plane)
__device__ __forceinline__ void cvt8_store_f16(float4 a, float4 b, char* hp) {
    uint32_t h0 = packf16(a.y, a.x);
    uint32_t h1 = packf16(a.w, a.z);
    uint32_t h2 = packf16(b.y, b.x);
    uint32_t h3 = packf16(b.w, b.z);
    *(uint4*)hp = make_uint4(h0, h1, h2, h3);
}

__global__ __launch_bounds__(NTH, 2)
void attn_hmma(const float* __restrict__ Q, const float* __restrict__ K,
               const float* __restrict__ V, float* __restrict__ Og) {
    extern __shared__ char smc[];
    const uint32_t sb = smem_u32(smc);
    const int tid = threadIdx.x;
    const int wid = tid >> 5;
    const int lane = tid & 31;
    const int g  = lane >> 2;         // quad row
    const int tg = lane & 3;          // quad col
    const int bh = blockIdx.y;
    const int bhoff = (bh >> 4) * 1024 + (bh & 15) * 64;
    const int qbase = blockIdx.x * BM;

    // ---- fill geometry: 128 threads cover a 64x64 tile in 4 chunks of 8 ----
    const int frow = tid >> 3, fd0 = (tid & 7) * 8;   // rows step +16 per chunk
    const size_t goffF = (size_t)frow * RSTRIDE + bhoff + fd0;
    const int soffF = (frow * LDH + fd0) * 2;

    // ---- Q tile fp32 -> bf16 hi/lo into smem (128 rows) ----
    #pragma unroll
    for (int i = 0; i < 8; i++) {
        int c = tid + NTH * i;                // 1024 chunks of 8 elems
        int row = c >> 3, d0 = (c & 7) * 8;
        const float* gq = Q + (size_t)(qbase + row) * RSTRIDE + bhoff + d0;
        float4 a = *(const float4*)gq;
        float4 b = *(const float4*)(gq + 4);
        int off = (row * LDH + d0) * 2;
        cvt8_store(a, b, smc + S_QH + off, smc + S_QL + off);
    }

    // ---- prologue: fill K/V tile 0 into buffer 0 ----
    {
        char* b0 = smc + S_KV0;
        #pragma unroll
        for (int i = 0; i < 4; i++) {
            const float* gk = K + goffF + (size_t)i * 16 * RSTRIDE;
            float4 a = *(const float4*)gk, b = *(const float4*)(gk + 4);
            cvt8_store(a, b, b0 + KH_REL + soffF + i * (16 * LDH * 2),
                             b0 + KL_REL + soffF + i * (16 * LDH * 2));
            const float* gv = V + goffF + (size_t)i * 16 * RSTRIDE;
            float4 av = *(const float4*)gv, bv = *(const float4*)(gv + 4);
            cvt8_store_f16(av, bv, b0 + VH_REL + soffF + i * (16 * LDH * 2));
        }
    }

    // ---- per-lane ldmatrix offsets ----
    const int lb8  = (lane >> 3) & 1;
    const int lb16 = (lane >> 4) & 1;
    const uint32_t aQb0 = sb + ((wid * 32 +      (lane & 15)) * LDH + 8 * lb16) * 2;
    const uint32_t aQb1 = sb + ((wid * 32 + 16 + (lane & 15)) * LDH + 8 * lb16) * 2;
    const uint32_t bKoff = ((8 * lb16 + (lane & 7)) * LDH + 8 * lb8) * 2;
    const uint32_t bVoff = ((8 * lb8 + (lane & 7)) * LDH + 8 * lb16) * 2;

    float o[2][8][4];
    #pragma unroll
    for (int bb = 0; bb < 2; bb++)
        #pragma unroll
        for (int j = 0; j < 8; j++)
            #pragma unroll
            for (int c = 0; c < 4; c++) o[bb][j][c] = 0.f;
    // row-sum accumulators via ones-GEMM: lsacc[bb][0..1] rows g, [2..3] rows g+8
    float lsacc[2][4];
    #pragma unroll
    for (int bb = 0; bb < 2; bb++)
        #pragma unroll
        for (int c = 0; c < 4; c++) lsacc[bb][c] = 0.f;
    float mrow[2][2] = {{-1e30f, -1e30f}, {-1e30f, -1e30f}};
    float nb[2][2]   = {{0.f, 0.f}, {0.f, 0.f}};   // mrow*LOG2E, lazily updated

    __syncthreads();   // Q smem + K/V buffer 0 visible

    for (int kt = 0; kt < NKT; kt++) {
        const uint32_t cur = sb + S_KV0 + (uint32_t)(kt & 1) * KVBUF;
        const uint32_t bK = cur + bKoff;
        const uint32_t bV = cur + bVoff;
        char* nx = smc + S_KV0 + ((kt + 1) & 1) * KVBUF;
        const bool haveNext = (kt + 1 < NKT);
        const size_t kb = (size_t)(kt + 1) * BN * RSTRIDE;
        float4 pA[4], pB[4];

        float s[2][8][4];
        #pragma unroll
        for (int bb = 0; bb < 2; bb++)
            #pragma unroll
            for (int j = 0; j < 8; j++)
                #pragma unroll
                for (int c = 0; c < 4; c++) s[bb][j][c] = 0.f;

        // ---- GEMM1: both row blocks share every K B-fragment ----
        #pragma unroll
        for (int kk = 0; kk < 4; kk++) {
            uint32_t aQH0[4], aQL0[4], aQH1[4], aQL1[4];
            LDSM4(aQH0[0], aQH0[1], aQH0[2], aQH0[3], aQb0 + S_QH + kk * 32);
            LDSM4(aQL0[0], aQL0[1], aQL0[2], aQL0[3], aQb0 + S_QL + kk * 32);
            LDSM4(aQH1[0], aQH1[1], aQH1[2], aQH1[3], aQb1 + S_QH + kk * 32);
            LDSM4(aQL1[0], aQL1[1], aQL1[2], aQL1[3], aQb1 + S_QL + kk * 32);
            #pragma unroll
            for (int j2 = 0; j2 < 4; j2++) {
                uint32_t b0, b1, b2, b3;
                LDSM4(b0, b1, b2, b3, bK + KH_REL + j2 * (16 * LDH * 2) + kk * 32);
                MMA16816(s[0][2 * j2],     aQH0, b0, b1);
                MMA16816(s[0][2 * j2 + 1], aQH0, b2, b3);
                MMA16816(s[1][2 * j2],     aQH1, b0, b1);
                MMA16816(s[1][2 * j2 + 1], aQH1, b2, b3);
                MMA16816(s[0][2 * j2],     aQL0, b0, b1);
                MMA16816(s[0][2 * j2 + 1], aQL0, b2, b3);
                MMA16816(s[1][2 * j2],     aQL1, b0, b1);
                MMA16816(s[1][2 * j2 + 1], aQL1, b2, b3);
                uint32_t c0, c1, c2, c3;
                LDSM4(c0, c1, c2, c3, bK + KL_REL + j2 * (16 * LDH * 2) + kk * 32);
                MMA16816(s[0][2 * j2],     aQH0, c0, c1);
                MMA16816(s[0][2 * j2 + 1], aQH0, c2, c3);
                MMA16816(s[1][2 * j2],     aQH1, c0, c1);
                MMA16816(s[1][2 * j2 + 1], aQH1, c2, c3);
            }
            if (kk == 0 && haveNext) {
                // issue next K global loads early
                #pragma unroll
                for (int i = 0; i < 4; i++) {
                    const float* gp = K + kb + goffF + (size_t)i * 16 * RSTRIDE;
                    pA[i] = *(const float4*)gp;
                    pB[i] = *(const float4*)(gp + 4);
                }
            }
        }

        // ---- prefetch G2 chunk-0 V fragments (independent of softmax) ----
        uint32_t vb[4][2], vc[4][2];
        #pragma unroll
        for (int j2 = 0; j2 < 4; j2++) {
            LDSM4T(vb[j2][0], vb[j2][1], vc[j2][0], vc[j2][1],
                   bV + VH_REL + 0 * (16 * LDH * 2) + j2 * 32);
        }

        // ---- lane-local maxima; full reduce + rescale only when grown ----
        float mx[2][2];
        #pragma unroll
        for (int bb = 0; bb < 2; bb++) {
            float mx0 = -1e30f, mx1 = -1e30f;
            #pragma unroll
            for (int j = 0; j < 8; j++) {
                mx0 = fmaxf(mx0, fmaxf(s[bb][j][0], s[bb][j][1]));
                mx1 = fmaxf(mx1, fmaxf(s[bb][j][2], s[bb][j][3]));
            }
            mx[bb][0] = mx0; mx[bb][1] = mx1;
        }
        const bool grew = (mx[0][0] > mrow[0][0]) | (mx[0][1] > mrow[0][1]) |
                          (mx[1][0] > mrow[1][0]) | (mx[1][1] > mrow[1][1]);
        if (__any_sync(0xffffffffu, grew)) {
            #pragma unroll
            for (int bb = 0; bb < 2; bb++) {
                float mx0 = mx[bb][0], mx1 = mx[bb][1];
                mx0 = fmaxf(mx0, __shfl_xor_sync(0xffffffffu, mx0, 1));
                mx0 = fmaxf(mx0, __shfl_xor_sync(0xffffffffu, mx0, 2));
                mx1 = fmaxf(mx1, __shfl_xor_sync(0xffffffffu, mx1, 1));
                mx1 = fmaxf(mx1, __shfl_xor_sync(0xffffffffu, mx1, 2));
                float mn0 = fmaxf(mrow[bb][0], mx0);
                float mn1 = fmaxf(mrow[bb][1], mx1);
                float corr0 = ex2((mrow[bb][0] - mn0) * LOG2E);
                float corr1 = ex2((mrow[bb][1] - mn1) * LOG2E);
                mrow[bb][0] = mn0; mrow[bb][1] = mn1;
                nb[bb][0] = mn0 * LOG2E; nb[bb][1] = mn1 * LOG2E;
                lsacc[bb][0] *= corr0; lsacc[bb][1] *= corr0;
                lsacc[bb][2] *= corr1; lsacc[bb][3] *= corr1;
                #pragma unroll
                for (int j = 0; j < 8; j++) {
                    o[bb][j][0] *= corr0; o[bb][j][1] *= corr0;
                    o[bb][j][2] *= corr1; o[bb][j][3] *= corr1;
                }
            }
        }

        // ---- phase 2: sm(kk+1) before G2(kk); p via ex2.approx.f16x2 ----
        uint32_t PH[2][2][4];   // [parity][block][frag]  (fp16 P)

        // sm chunk 0 -> parity 0
        #pragma unroll
        for (int bb = 0; bb < 2; bb++) {
            float* s0 = s[bb][0];
            float* s1 = s[bb][1];
            float t00 = fmaf(s0[0], LOG2E, -nb[bb][0]);
            float t01 = fmaf(s0[1], LOG2E, -nb[bb][0]);
            float t02 = fmaf(s0[2], LOG2E, -nb[bb][1]);
            float t03 = fmaf(s0[3], LOG2E, -nb[bb][1]);
            float t10 = fmaf(s1[0], LOG2E, -nb[bb][0]);
            float t11 = fmaf(s1[1], LOG2E, -nb[bb][0]);
            float t12 = fmaf(s1[2], LOG2E, -nb[bb][1]);
            float t13 = fmaf(s1[3], LOG2E, -nb[bb][1]);
            PH[0][bb][0] = h2ex2(packf16(t01, t00));
            PH[0][bb][1] = h2ex2(packf16(t03, t02));
            PH[0][bb][2] = h2ex2(packf16(t11, t10));
            PH[0][bb][3] = h2ex2(packf16(t13, t12));
        }

        #pragma unroll
        for (int kk = 0; kk < 4; kk++) {
            const int pc = kk & 1, pn = (kk + 1) & 1;

            // sm chunk kk+1 -> parity pn (hides under G2(kk) MMA drain below)
            if (kk < 3) {
                const int j = 2 * (kk + 1), j1 = 2 * (kk + 1) + 1;
                #pragma unroll
                for (int bb = 0; bb < 2; bb++) {
                    float* s0 = s[bb][j];
                    float* s1 = s[bb][j1];
                    float t00 = fmaf(s0[0], LOG2E, -nb[bb][0]);
                    float t01 = fmaf(s0[1], LOG2E, -nb[bb][0]);
                    float t02 = fmaf(s0[2], LOG2E, -nb[bb][1]);
                    float t03 = fmaf(s0[3], LOG2E, -nb[bb][1]);
                    float t10 = fmaf(s1[0], LOG2E, -nb[bb][0]);
                    float t11 = fmaf(s1[1], LOG2E, -nb[bb][0]);
                    float t12 = fmaf(s1[2], LOG2E, -nb[bb][1]);
                    float t13 = fmaf(s1[3], LOG2E, -nb[bb][1]);
                    PH[pn][bb][0] = h2ex2(packf16(t01, t00));
                    PH[pn][bb][1] = h2ex2(packf16(t03, t02));
                    PH[pn][bb][2] = h2ex2(packf16(t11, t10));
                    PH[pn][bb][3] = h2ex2(packf16(t13, t12));
                }
            }

            if (kk == 1 && haveNext) {
                // store next K (nx safe: last read ended before iter-kt barrier)
                #pragma unroll
                for (int i = 0; i < 4; i++)
                    cvt8_store(pA[i], pB[i],
                               nx + KH_REL + soffF + i * (16 * LDH * 2),
                               nx + KL_REL + soffF + i * (16 * LDH * 2));
                // issue next V loads
                #pragma unroll
                for (int i = 0; i < 4; i++) {
                    const float* gp = V + kb + goffF + (size_t)i * 16 * RSTRIDE;
                    pA[i] = *(const float4*)gp;
                    pB[i] = *(const float4*)(gp + 4);
                }
            }
            if (kk == 3 && haveNext) {
                // store next V (current G2 reads cur buffer, no conflict)
                #pragma unroll
                for (int i = 0; i < 4; i++)
                    cvt8_store_f16(pA[i], pB[i],
                                   nx + VH_REL + soffF + i * (16 * LDH * 2));
            }

            // G2 chunk kk: O += P_f16 . V_f16  [parity pc]
            if (kk == 0) {
                #pragma unroll
                for (int j2 = 0; j2 < 4; j2++) {
                    MMAH16816(o[0][2 * j2],     PH[0][0], vb[j2][0], vb[j2][1]);
                    MMAH16816(o[0][2 * j2 + 1], PH[0][0], vc[j2][0], vc[j2][1]);
                    MMAH16816(o[1][2 * j2],     PH[0][1], vb[j2][0], vb[j2][1]);
                    MMAH16816(o[1][2 * j2 + 1], PH[0][1], vc[j2][0], vc[j2][1]);
                }
            } else {
                #pragma unroll
                for (int j2 = 0; j2 < 4; j2++) {
                    uint32_t b0, b1, b2, b3;
                    LDSM4T(b0, b1, b2, b3, bV + VH_REL + kk * (16 * LDH * 2) + j2 * 32);
                    MMAH16816(o[0][2 * j2],     PH[pc][0], b0, b1);
                    MMAH16816(o[0][2 * j2 + 1], PH[pc][0], b2, b3);
                    MMAH16816(o[1][2 * j2],     PH[pc][1], b0, b1);
                    MMAH16816(o[1][2 * j2 + 1], PH[pc][1], b2, b3);
                }
            }
            // row sums: lsacc += P(chunk kk) . ones  (every column = row sum)
            MMAH16816(lsacc[0], PH[pc][0], ONESF16, ONESF16);
            MMAH16816(lsacc[1], PH[pc][1], ONESF16, ONESF16);
        }

        if (haveNext) __syncthreads();
    }

    // ---- epilogue: lsacc already holds full row sums (no shuffles) ----
    #pragma unroll
    for (int bb = 0; bb < 2; bb++) {
        float inv0 = 1.f / lsacc[bb][0];
        float inv1 = 1.f / lsacc[bb][2];
        const int orow = qbase + wid * 32 + bb * 16 + g;
        float* d0p = Og + (size_t)orow * RSTRIDE + bhoff + 2 * tg;
        float* d1p = d0p + 8 * RSTRIDE;
        #pragma unroll
        for (int j = 0; j < 8; j++) {
            *(float2*)(d0p + 8 * j) = make_float2(o[bb][j][0] * inv0, o[bb][j][1] * inv0);
            *(float2*)(d1p + 8 * j) = make_float2(o[bb][j][2] * inv1, o[bb][j][3] * inv1);
        }
    }
}

extern "C" void kernel_launch(void* const* d_in, const int* in_sizes, int n_in,
                              void* d_out, int out_size) {
    const float* Q = (const float*)d_in[0];
    const float* K = (const float*)d_in[1];
    const float* V = (const float*)d_in[2];
    float* O = (float*)d_out;

    cudaFuncSetAttribute(attn_hmma, cudaFuncAttributeMaxDynamicSharedMemorySize, SMEM_TOTAL);
    dim3 grid(SQc / BM, 32);
    attn_hmma<<<grid, NTH, SMEM_TOTAL>>>(Q, K, V, O);
}